// round 12
// baseline (speedup 1.0000x reference)
#include <cuda_runtime.h>
#include <cuda_bf16.h>
#include <cstdint>

// VectorQuantizer via warp-level mma.sync (HMMA) bf16-split GEMM.
// (tcgen05 unavailable: harness compiles PTX at base .target sm_103.)
//
// x [8,2048,512] f32, codebook [8,1024,64] f32.
// argmin_k ||x-c_k||^2 == argmax_k ( (2x)·c_k - ||c_k||^2 )
// Cross term: 3-way bf16 split of (2x) and c, 6 product pairs on
// mma.sync.m16n8k16.row.col.f32.bf16.bf16.f32. Score error ~6e-7 abs,
// below the fp32 reference's own rounding noise (zero flips in R1-R10).
// Output gathers exact fp32 codebook rows -> rel_err 0.0 iff no flips.
//
// CTA: 128 tokens x 1 group, 8 chunks of 128 codes.
// 8 warps in 4x2: warp = (mrow = wid&3 -> 32 tokens, ncol = wid>>2 -> 64 codes).
// Per warp per chunk: Mfrag2 x Nfrag8 x K4 x 6 pairs = 384 mma, 64 f32 accum.

#define NUM_TOKENS 16384
#define DFULL      512
#define DG         64
#define KCODES     1024
#define NGROUPS    8
#define MTILE      128
#define CODE_CHUNK 128
#define NCHUNK     (KCODES / CODE_CHUNK)
#define THREADS    256

// dynamic smem (bytes):
#define OFF_CN      64        // 128 f32 chunk code norms (reused as fin[] at end)
#define OFF_CV      576       // 256 f32 candidate vals
#define OFF_CI      1600      // 256 i32 candidate idxs
#define OFF_A       3072      // 3 x 16384, 1024-aligned
#define OFF_B       52224     // 3 x 16384
#define SPLIT_BYTES 16384
#define SMEM_TOTAL  101376

#define SW128(o) ((o) ^ ((((uint32_t)(o)) >> 3) & 0x70u))

extern __shared__ char smem_raw[];

__device__ __forceinline__ uint32_t smem_u32(const void* p) {
    uint32_t a;
    asm("{ .reg .u64 t; cvta.to.shared.u64 t, %1; cvt.u32.u64 %0, t; }"
        : "=r"(a) : "l"(p));
    return a;
}

__device__ __forceinline__ uint32_t pack_bf16x2(__nv_bfloat16 lo, __nv_bfloat16 hi) {
    return (uint32_t)__bfloat16_as_ushort(lo) |
           ((uint32_t)__bfloat16_as_ushort(hi) << 16);
}

// 3-way bf16 split of two adjacent-k values; one 4B store per split buffer.
__device__ __forceinline__ void split3_store2(char* base, uint32_t sw_off,
                                              float v0, float v1) {
    __nv_bfloat16 a1 = __float2bfloat16(v0);
    __nv_bfloat16 b1 = __float2bfloat16(v1);
    float ra = v0 - __bfloat162float(a1);
    float rb = v1 - __bfloat162float(b1);
    __nv_bfloat16 a2 = __float2bfloat16(ra);
    __nv_bfloat16 b2 = __float2bfloat16(rb);
    float ra2 = ra - __bfloat162float(a2);
    float rb2 = rb - __bfloat162float(b2);
    __nv_bfloat16 a3 = __float2bfloat16(ra2);
    __nv_bfloat16 b3 = __float2bfloat16(rb2);
    *(uint32_t*)(base + 0 * SPLIT_BYTES + sw_off) = pack_bf16x2(a1, b1);
    *(uint32_t*)(base + 1 * SPLIT_BYTES + sw_off) = pack_bf16x2(a2, b2);
    *(uint32_t*)(base + 2 * SPLIT_BYTES + sw_off) = pack_bf16x2(a3, b3);
}

__device__ __forceinline__ void ldmx4(uint32_t addr, uint32_t& r0, uint32_t& r1,
                                      uint32_t& r2, uint32_t& r3) {
    asm volatile("ldmatrix.sync.aligned.m8n8.x4.shared.b16 {%0,%1,%2,%3}, [%4];"
                 : "=r"(r0), "=r"(r1), "=r"(r2), "=r"(r3) : "r"(addr));
}
__device__ __forceinline__ void ldmx2(uint32_t addr, uint32_t& r0, uint32_t& r1) {
    asm volatile("ldmatrix.sync.aligned.m8n8.x2.shared.b16 {%0,%1}, [%2];"
                 : "=r"(r0), "=r"(r1) : "r"(addr));
}
__device__ __forceinline__ void mma16816(float* d, uint32_t a0, uint32_t a1,
                                         uint32_t a2, uint32_t a3,
                                         uint32_t b0, uint32_t b1) {
    asm volatile("mma.sync.aligned.m16n8k16.row.col.f32.bf16.bf16.f32 "
                 "{%0,%1,%2,%3}, {%4,%5,%6,%7}, {%8,%9}, {%0,%1,%2,%3};"
                 : "+f"(d[0]), "+f"(d[1]), "+f"(d[2]), "+f"(d[3])
                 : "r"(a0), "r"(a1), "r"(a2), "r"(a3), "r"(b0), "r"(b1));
}

__global__ __launch_bounds__(THREADS, 2)
void vq_kernel(const float* __restrict__ x,
               const float* __restrict__ cb,
               float* __restrict__ out)
{
    char* sm = smem_raw;
    const uint32_t smem_base = smem_u32(sm);
    float* cn  = (float*)(sm + OFF_CN);
    float* cv  = (float*)(sm + OFF_CV);
    int*   ci  = (int*)(sm + OFF_CI);
    int*   fin = (int*)(sm + OFF_CN);   // reused after chunks

    const int g    = blockIdx.y;
    const int t0   = blockIdx.x * MTILE;
    const int tid  = threadIdx.x;
    const int wid  = tid >> 5;
    const int lane = tid & 31;
    const int mrow = wid & 3;           // token group: mrow*32
    const int ncol = wid >> 2;          // code half:  ncol*64

    const float* cbg = cb + (size_t)g * KCODES * DG;

    // ---- build A: 2x tile, 3-way bf16 split, SW128 [128 tok x 64 k] ----
    {
        const int row  = tid >> 1;
        const int half = tid & 1;       // 32 floats each
        const float* xp = x + (size_t)(t0 + row) * DFULL + g * DG + half * 32;
        #pragma unroll
        for (int q = 0; q < 8; q++) {
            float4 v = *(const float4*)(xp + q * 4);
            int col = half * 32 + q * 4;
            split3_store2(sm + OFF_A, SW128(row * 128 + (col + 0) * 2),
                          2.0f * v.x, 2.0f * v.y);
            split3_store2(sm + OFF_A, SW128(row * 128 + (col + 2) * 2),
                          2.0f * v.z, 2.0f * v.w);
        }
    }
    __syncthreads();

    // per-thread running argmax for 4 token-rows:
    // r = mf*2 + h -> token mrow*32 + mf*16 + h*8 + (lane>>2)
    float best[4] = {-1e30f, -1e30f, -1e30f, -1e30f};
    int   bidx[4] = {0, 0, 0, 0};

    const int SA[6] = {0, 0, 1, 1, 0, 2};
    const int SB[6] = {0, 1, 0, 1, 2, 0};

    for (int ch = 0; ch < NCHUNK; ch++) {
        const int c0 = ch * CODE_CHUNK;

        // ---- build B: codebook chunk split + norms ----
        {
            const int code = tid >> 1;
            const int half = tid & 1;
            const float* cp = cbg + (size_t)(c0 + code) * DG + half * 32;
            float nrm = 0.f;
            #pragma unroll
            for (int q = 0; q < 8; q++) {
                float4 v = *(const float4*)(cp + q * 4);
                nrm += v.x * v.x + v.y * v.y + v.z * v.z + v.w * v.w;
                int col = half * 32 + q * 4;
                split3_store2(sm + OFF_B, SW128(code * 128 + (col + 0) * 2),
                              v.x, v.y);
                split3_store2(sm + OFF_B, SW128(code * 128 + (col + 2) * 2),
                              v.z, v.w);
            }
            float other = __shfl_xor_sync(0xffffffffu, nrm, 1);
            if (half == 0) cn[code] = nrm + other;
        }
        __syncthreads();

        // ---- GEMM: D[32 tok x 64 codes] per warp, 6 split pairs ----
        float acc[2][8][4];
        #pragma unroll
        for (int mf = 0; mf < 2; mf++)
            #pragma unroll
            for (int nf = 0; nf < 8; nf++)
                #pragma unroll
                for (int q = 0; q < 4; q++)
                    acc[mf][nf][q] = 0.f;

        for (int s = 0; s < 6; s++) {
            const uint32_t abase = smem_base + OFF_A + SA[s] * SPLIT_BYTES;
            const uint32_t bbase = smem_base + OFF_B + SB[s] * SPLIT_BYTES;
            #pragma unroll
            for (int k4 = 0; k4 < 4; k4++) {
                uint32_t a[2][4];
                #pragma unroll
                for (int mf = 0; mf < 2; mf++) {
                    uint32_t off = (uint32_t)(mrow * 32 + mf * 16 + (lane & 15)) * 128
                                 + k4 * 32 + (lane >> 4) * 16;
                    ldmx4(abase + SW128(off), a[mf][0], a[mf][1], a[mf][2], a[mf][3]);
                }
                #pragma unroll
                for (int nf = 0; nf < 8; nf++) {
                    uint32_t off = (uint32_t)(ncol * 64 + nf * 8 + (lane & 7)) * 128
                                 + k4 * 32 + ((lane >> 3) & 1) * 16;
                    uint32_t b0, b1;
                    ldmx2(bbase + SW128(off), b0, b1);
                    mma16816(acc[0][nf], a[0][0], a[0][1], a[0][2], a[0][3], b0, b1);
                    mma16816(acc[1][nf], a[1][0], a[1][1], a[1][2], a[1][3], b0, b1);
                }
            }
        }

        // ---- scores: D - ||c||^2, update running argmax ----
        // thread cell: row_lo = mf*16 + lane>>2 (d0,d1), row_hi = +8 (d2,d3)
        // col = ncol*64 + nf*8 + (lane&3)*2 + {0,1}
        #pragma unroll
        for (int nf = 0; nf < 8; nf++) {
            const int cl = ncol * 64 + nf * 8 + (lane & 3) * 2;
            const float n0 = cn[cl], n1 = cn[cl + 1];
            const int code0 = c0 + cl;
            #pragma unroll
            for (int mf = 0; mf < 2; mf++) {
                float s0 = acc[mf][nf][0] - n0;
                float s1 = acc[mf][nf][1] - n1;
                float s2 = acc[mf][nf][2] - n0;
                float s3 = acc[mf][nf][3] - n1;
                const int rlo = mf * 2, rhi = mf * 2 + 1;
                if (s0 > best[rlo]) { best[rlo] = s0; bidx[rlo] = code0; }
                if (s1 > best[rlo]) { best[rlo] = s1; bidx[rlo] = code0 + 1; }
                if (s2 > best[rhi]) { best[rhi] = s2; bidx[rhi] = code0; }
                if (s3 > best[rhi]) { best[rhi] = s3; bidx[rhi] = code0 + 1; }
            }
        }
        __syncthreads();   // all reads of cn/B done before next chunk rewrite
    }

    // ---- reduce across the 4 lanes of each row-quad, then across halves ----
    #pragma unroll
    for (int r = 0; r < 4; r++) {
        float v = best[r];
        int   ix = bidx[r];
        #pragma unroll
        for (int m = 1; m <= 2; m <<= 1) {
            float ov = __shfl_xor_sync(0xffffffffu, v, m);
            int   oi = __shfl_xor_sync(0xffffffffu, ix, m);
            if (ov > v || (ov == v && oi < ix)) { v = ov; ix = oi; }
        }
        if ((lane & 3) == 0) {
            int tok = mrow * 32 + (r >> 1) * 16 + (r & 1) * 8 + (lane >> 2);
            cv[ncol * 128 + tok] = v;
            ci[ncol * 128 + tok] = ix;
        }
    }
    __syncthreads();
    if (tid < MTILE) {
        float v0 = cv[tid];        int i0 = ci[tid];
        float v1 = cv[128 + tid];  int i1 = ci[128 + tid];
        fin[tid] = (v1 > v0 || (v1 == v0 && i1 < i0)) ? i1 : i0;
    }
    __syncthreads();

    // ---- gather winning code (exact fp32), out = x + (c - x) ----
    {
        const int row  = tid >> 1;
        const int half = tid & 1;
        const int code = fin[row];
        const float* cp = cbg + (size_t)code * DG + half * 32;
        const float* xp = x   + (size_t)(t0 + row) * DFULL + g * DG + half * 32;
        float*       op = out + (size_t)(t0 + row) * DFULL + g * DG + half * 32;
        #pragma unroll
        for (int q = 0; q < 8; q++) {
            float4 c4 = *(const float4*)(cp + q * 4);
            float4 x4 = *(const float4*)(xp + q * 4);
            float4 o;
            o.x = x4.x + (c4.x - x4.x);
            o.y = x4.y + (c4.y - x4.y);
            o.z = x4.z + (c4.z - x4.z);
            o.w = x4.w + (c4.w - x4.w);
            *(float4*)(op + q * 4) = o;
        }
    }
}

extern "C" void kernel_launch(void* const* d_in, const int* in_sizes, int n_in,
                              void* d_out, int out_size)
{
    const float* x  = (const float*)d_in[0];   // [8,2048,512]
    const float* cb = (const float*)d_in[1];   // [8,1024,64]
    float* out = (float*)d_out;

    static int configured = 0;
    if (!configured) {
        cudaFuncSetAttribute(vq_kernel,
                             cudaFuncAttributeMaxDynamicSharedMemorySize,
                             SMEM_TOTAL);
        configured = 1;
    }

    dim3 grid(NUM_TOKENS / MTILE, NGROUPS);    // (128, 8)
    vq_kernel<<<grid, THREADS, SMEM_TOTAL>>>(x, cb, out);
}